// round 6
// baseline (speedup 1.0000x reference)
#include <cuda_runtime.h>
#include <cuda_bf16.h>
#include <cstdint>

// ---------------------------------------------------------------------------
// CrystalDecoder on GB300 (sm_103a via compute_103 PTX -> HMMA mma.sync only)
// Node path: 16-warp pair-autonomous bf16 hi/lo compensated mma.sync GEMM,
//            fragment-layout weights (LDS.128), cross-tile X prefetch,
//            fused edge-gather tail.
// Edge path: algebraic collapse to 256x256 lookup table + gather.
// ---------------------------------------------------------------------------

#define MAXB 256

__device__ float  g_zb[MAXB * 64];      // z_proj @ nd1_w + nd1_b
__device__ float  g_As[MAXB * 64];
__device__ float  g_Bd[MAXB * 64];
__device__ float4 g_table[MAXB * MAXB];

// fragment-layout weights: uint4{bh0,bh1,bl0,bl1} per (nt, s, lane)
__device__ uint4 g_w1f[16 * 8 * 32];    // 64 KB
__device__ uint4 g_w2f[8 * 8 * 32];     // 32 KB

// u32 stride 68: (68*g + 8s + tg) mod 32 = (4g+tg) -> perfect bank permutation
#define XS 68
#define ZS 68

#define MMA16816(c, a, b0, b1) \
    asm volatile("mma.sync.aligned.m16n8k16.row.col.f32.bf16.bf16.f32 " \
        "{%0,%1,%2,%3}, {%4,%5,%6,%7}, {%8,%9}, {%0,%1,%2,%3};" \
        : "+f"((c)[0]), "+f"((c)[1]), "+f"((c)[2]), "+f"((c)[3]) \
        : "r"((a)[0]), "r"((a)[1]), "r"((a)[2]), "r"((a)[3]), "r"(b0), "r"(b1))

#define PAIR_BAR(id) asm volatile("bar.sync %0, 64;" :: "r"(id) : "memory")

__device__ __forceinline__ uint32_t pkbf(float a, float b) {
    __nv_bfloat162 t = __floats2bfloat162_rn(a, b);
    return *(uint32_t*)&t;
}

// ---------------------------------------------------------------------------
// Weight conversion into fragment layout.
// For (nt, s, lane=g*4+tg): n = nt*8+g, k0 = 16s+2tg, k1 = k0+8.
// bh0 = hi(W^T[n][k0..k0+1]), bh1 = hi(W^T[n][k1..k1+1]); bl* = lo parts.
// ---------------------------------------------------------------------------
__device__ __forceinline__ void split2(float v0, float v1, uint32_t& hi, uint32_t& lo) {
    float h0 = __bfloat162float(__float2bfloat16(v0));
    float h1 = __bfloat162float(__float2bfloat16(v1));
    hi = pkbf(h0, h1);
    lo = pkbf(v0 - h0, v1 - h1);
}

__global__ void wconv_kernel(const float* __restrict__ w1, const float* __restrict__ w2)
{
    int i = blockIdx.x * blockDim.x + threadIdx.x;   // 0..6143
    if (i < 4096) {
        int lane = i & 31, s = (i >> 5) & 7, nt = i >> 8;
        int g = lane >> 2, tg = lane & 3;
        int n = nt * 8 + g;
        int k0 = 16 * s + 2 * tg;
        int k1 = k0 + 8;
        // w1 is [k][n] row-major (k-major): W^T[n][k] = w1[k*128+n]
        uint32_t bh0, bl0, bh1, bl1;
        split2(w1[k0 * 128 + n], w1[(k0 + 1) * 128 + n], bh0, bl0);
        split2(w1[k1 * 128 + n], w1[(k1 + 1) * 128 + n], bh1, bl1);
        g_w1f[i] = make_uint4(bh0, bh1, bl0, bl1);
    }
    if (i < 2048) {
        int lane = i & 31, s = (i >> 5) & 7, nt = i >> 8;
        int g = lane >> 2, tg = lane & 3;
        int n = nt * 8 + g;      // < 64
        int k0 = 16 * s + 2 * tg;
        int k1 = k0 + 8;
        uint32_t bh0, bl0, bh1, bl1;
        split2(w2[k0 * 64 + n], w2[(k0 + 1) * 64 + n], bh0, bl0);
        split2(w2[k1 * 64 + n], w2[(k1 + 1) * 64 + n], bh1, bl1);
        g_w2f[i] = make_uint4(bh0, bh1, bl0, bl1);
    }
}

// ---------------------------------------------------------------------------
// Persistent node kernel + fused edge gather tail. 512 threads, 8 pairs.
// ---------------------------------------------------------------------------
#define NODE_SMEM_U32 (4096*4 + 2048*4 + 2*128*XS + 128*ZS + 128 + 256)
#define NODE_SMEM_BYTES (NODE_SMEM_U32 * 4)

__global__ void __launch_bounds__(512, 1)
node_mma_kernel(const float* __restrict__ node_emb, const int* __restrict__ graph_id,
                const float* __restrict__ b1,
                const float* __restrict__ w3, const float* __restrict__ b3,
                float* __restrict__ out_node, int N, int ntiles,
                const int* __restrict__ src, const int* __restrict__ dst,
                float* __restrict__ out_edge, int E)
{
    extern __shared__ uint32_t su[];
    uint4*    sW1f = (uint4*)su;                 // [16*8*32]
    uint4*    sW2f = sW1f + 4096;                // [8*8*32]
    uint32_t* sXh  = su + 4096 * 4 + 2048 * 4;   // [128][XS]
    uint32_t* sXl  = sXh + 128 * XS;             // [128][XS]; merge aliases pair rows
    float*    szb  = (float*)(sXl + 128 * XS);   // [128][ZS]
    float*    sB1  = szb + 128 * ZS;             // [128]
    float*    sW3  = sB1 + 128;                  // [64][4]

    const int tid  = threadIdx.x;
    const int lane = tid & 31;
    const int w    = tid >> 5;       // 0..15
    const int p    = w >> 1;         // pair 0..7
    const int h    = w & 1;          // half
    const int g    = lane >> 2;
    const int tg   = lane & 3;
    const int r0   = p * 16;
    const int u    = tid & 63;       // thread within pair
    const int barid = p + 1;
    float* mrg = (float*)(sXl + p * 1088);   // 1024 floats inside own pair rows

    // ---- one-time staging (block-wide) ----
    for (int i = tid; i < 4096; i += 512) sW1f[i] = g_w1f[i];
    for (int i = tid; i < 2048; i += 512) sW2f[i] = g_w2f[i];
    if (tid < 128) sB1[tid] = b1[tid];
    else if (tid >= 256 && tid < 320) ((float4*)sW3)[tid - 256] = ((const float4*)w3)[tid - 256];
    const float b30 = b3[0], b31 = b3[1], b32 = b3[2], b33 = b3[3];

    // ---- prologue: stage tile0 (pair-local rows only) ----
    int tile = blockIdx.x;
    if (tile < ntiles) {
        const int base = tile * 128;
        #pragma unroll
        for (int it = 0; it < 8; it++) {
            int idx = it * 64 + u;
            int row = r0 + (idx >> 5);
            int q   = idx & 31;
            int gn  = base + row;
            float4 v = (gn < N) ? ((const float4*)(node_emb + (size_t)gn * 128))[q]
                                : make_float4(0.f, 0.f, 0.f, 0.f);
            float hx = __bfloat162float(__float2bfloat16(v.x));
            float hy = __bfloat162float(__float2bfloat16(v.y));
            float hz = __bfloat162float(__float2bfloat16(v.z));
            float hw = __bfloat162float(__float2bfloat16(v.w));
            *(uint2*)&sXh[row * XS + 2 * q] = make_uint2(pkbf(hx, hy), pkbf(hz, hw));
            *(uint2*)&sXl[row * XS + 2 * q] = make_uint2(pkbf(v.x - hx, v.y - hy),
                                                         pkbf(v.z - hz, v.w - hw));
        }
        {
            int row = r0 + (u >> 2);
            int gn  = base + row;
            int gid = (gn < N) ? graph_id[gn] : 0;
            const float4* z4 = (const float4*)(g_zb + gid * 64);
            #pragma unroll
            for (int qq = 0; qq < 4; qq++) {
                int q = (u & 3) * 4 + qq;
                ((float4*)(szb + row * ZS))[q] = z4[q];
            }
        }
    }
    __syncthreads();   // only block-wide sync

    for (; tile < ntiles; tile += gridDim.x) {
        const int base = tile * 128;

        // ---- Layer 1: 8 n-tiles (global nt = 8h+j), all 8 k-steps ----
        float acc[8][4];
        #pragma unroll
        for (int j = 0; j < 8; j++)
            #pragma unroll
            for (int q = 0; q < 4; q++) acc[j][q] = 0.f;

        const uint32_t* xh0 = &sXh[(r0 + g) * XS];
        const uint32_t* xh1 = &sXh[(r0 + g + 8) * XS];
        const uint32_t* xl0 = &sXl[(r0 + g) * XS];
        const uint32_t* xl1 = &sXl[(r0 + g + 8) * XS];

        #pragma unroll
        for (int s = 0; s < 8; s++) {
            const int o = s * 8 + tg;
            uint32_t aH[4] = { xh0[o], xh1[o], xh0[o + 4], xh1[o + 4] };
            uint32_t aL[4] = { xl0[o], xl1[o], xl0[o + 4], xl1[o + 4] };
            #pragma unroll
            for (int j = 0; j < 8; j++) {
                uint4 b = sW1f[((8 * h + j) * 8 + s) * 32 + lane];
                MMA16816(acc[j], aH, b.x, b.y);
                MMA16816(acc[j], aH, b.z, b.w);
                MMA16816(acc[j], aL, b.x, b.y);
            }
        }
        PAIR_BAR(barid);   // barA: pair done reading its sX rows

        // ---- prefetch next tile's X into registers ----
        const int  ntile = tile + gridDim.x;
        const bool nv    = ntile < ntiles;
        float4 xp[8];
        if (nv) {
            const int nbase = ntile * 128;
            #pragma unroll
            for (int it = 0; it < 8; it++) {
                int idx = it * 64 + u;
                int row = r0 + (idx >> 5);
                int q   = idx & 31;
                int gn  = nbase + row;
                xp[it] = (gn < N) ? ((const float4*)(node_emb + (size_t)gn * 128))[q]
                                  : make_float4(0.f, 0.f, 0.f, 0.f);
            }
        }

        // ---- epilogue 1 (registers): bias+relu, bf16 hi/lo -> A2 frags ----
        uint32_t a2h[4][4], a2l[4][4];
        #pragma unroll
        for (int s2 = 0; s2 < 4; s2++) {
            int cA = (4 * h + s2) * 16 + tg * 2;
            int cB = cA + 8;
            float bA0 = sB1[cA], bA1 = sB1[cA + 1];
            float bB0 = sB1[cB], bB1 = sB1[cB + 1];
            {
                float x0 = fmaxf(acc[2 * s2][0] + bA0, 0.f);
                float x1 = fmaxf(acc[2 * s2][1] + bA1, 0.f);
                split2(x0, x1, a2h[s2][0], a2l[s2][0]);
            }
            {
                float x0 = fmaxf(acc[2 * s2][2] + bA0, 0.f);
                float x1 = fmaxf(acc[2 * s2][3] + bA1, 0.f);
                split2(x0, x1, a2h[s2][1], a2l[s2][1]);
            }
            {
                float x0 = fmaxf(acc[2 * s2 + 1][0] + bB0, 0.f);
                float x1 = fmaxf(acc[2 * s2 + 1][1] + bB1, 0.f);
                split2(x0, x1, a2h[s2][2], a2l[s2][2]);
            }
            {
                float x0 = fmaxf(acc[2 * s2 + 1][2] + bB0, 0.f);
                float x1 = fmaxf(acc[2 * s2 + 1][3] + bB1, 0.f);
                split2(x0, x1, a2h[s2][3], a2l[s2][3]);
            }
        }

        // ---- Layer 2: all 8 n-tiles, local k-half (4 steps) -> partial ----
        float acc2[8][4];
        #pragma unroll
        for (int j = 0; j < 8; j++)
            #pragma unroll
            for (int q = 0; q < 4; q++) acc2[j][q] = 0.f;

        #pragma unroll
        for (int s = 0; s < 4; s++) {
            const int sg = 4 * h + s;
            #pragma unroll
            for (int j = 0; j < 8; j++) {
                uint4 b = sW2f[(j * 8 + sg) * 32 + lane];
                MMA16816(acc2[j], a2h[s], b.x, b.y);
                MMA16816(acc2[j], a2h[s], b.z, b.w);
                MMA16816(acc2[j], a2l[s], b.x, b.y);
            }
        }

        // ---- pair merge (buffer aliased onto own pair's dead sXl rows) ----
        if (h == 0) {
            #pragma unroll
            for (int j = 0; j < 8; j++)
                #pragma unroll
                for (int q = 0; q < 4; q++)
                    mrg[(j * 4 + q) * 32 + lane] = acc2[j][q];
        }
        PAIR_BAR(barid);   // barB

        if (h == 1) {
            #pragma unroll
            for (int j = 0; j < 8; j++)
                #pragma unroll
                for (int q = 0; q < 4; q++)
                    acc2[j][q] += mrg[(j * 4 + q) * 32 + lane];

            const int rA = r0 + g;
            const int rB = rA + 8;
            float oA0 = 0.f, oA1 = 0.f, oA2 = 0.f, oA3 = 0.f;
            float oB0 = 0.f, oB1 = 0.f, oB2 = 0.f, oB3 = 0.f;
            #pragma unroll
            for (int nt = 0; nt < 8; nt++) {
                int c0 = nt * 8 + tg * 2;
                int c1 = c0 + 1;
                float hA0 = fmaxf(acc2[nt][0] + szb[rA * ZS + c0], 0.f);
                float hA1 = fmaxf(acc2[nt][1] + szb[rA * ZS + c1], 0.f);
                float hB0 = fmaxf(acc2[nt][2] + szb[rB * ZS + c0], 0.f);
                float hB1 = fmaxf(acc2[nt][3] + szb[rB * ZS + c1], 0.f);
                float4 w0 = *(const float4*)&sW3[c0 * 4];
                float4 w1 = *(const float4*)&sW3[c1 * 4];
                oA0 = fmaf(hA0, w0.x, fmaf(hA1, w1.x, oA0));
                oA1 = fmaf(hA0, w0.y, fmaf(hA1, w1.y, oA1));
                oA2 = fmaf(hA0, w0.z, fmaf(hA1, w1.z, oA2));
                oA3 = fmaf(hA0, w0.w, fmaf(hA1, w1.w, oA3));
                oB0 = fmaf(hB0, w0.x, fmaf(hB1, w1.x, oB0));
                oB1 = fmaf(hB0, w0.y, fmaf(hB1, w1.y, oB1));
                oB2 = fmaf(hB0, w0.z, fmaf(hB1, w1.z, oB2));
                oB3 = fmaf(hB0, w0.w, fmaf(hB1, w1.w, oB3));
            }
            #pragma unroll
            for (int d = 1; d <= 2; d <<= 1) {
                oA0 += __shfl_xor_sync(0xFFFFFFFF, oA0, d);
                oA1 += __shfl_xor_sync(0xFFFFFFFF, oA1, d);
                oA2 += __shfl_xor_sync(0xFFFFFFFF, oA2, d);
                oA3 += __shfl_xor_sync(0xFFFFFFFF, oA3, d);
                oB0 += __shfl_xor_sync(0xFFFFFFFF, oB0, d);
                oB1 += __shfl_xor_sync(0xFFFFFFFF, oB1, d);
                oB2 += __shfl_xor_sync(0xFFFFFFFF, oB2, d);
                oB3 += __shfl_xor_sync(0xFFFFFFFF, oB3, d);
            }
            if (tg == 0) {
                int nA = base + rA;
                if (nA < N)
                    *(float4*)&out_node[(size_t)nA * 4] =
                        make_float4(oA0 + b30, oA1 + b31, oA2 + b32, oA3 + b33);
                int nB = base + rB;
                if (nB < N)
                    *(float4*)&out_node[(size_t)nB * 4] =
                        make_float4(oB0 + b30, oB1 + b31, oB2 + b32, oB3 + b33);
            }
        }

        // ---- write next X hi (sXh dead since barA) ----
        if (nv) {
            #pragma unroll
            for (int it = 0; it < 8; it++) {
                int idx = it * 64 + u;
                int row = r0 + (idx >> 5);
                int q   = idx & 31;
                float4 v = xp[it];
                float hx = __bfloat162float(__float2bfloat16(v.x));
                float hy = __bfloat162float(__float2bfloat16(v.y));
                float hz = __bfloat162float(__float2bfloat16(v.z));
                float hw = __bfloat162float(__float2bfloat16(v.w));
                *(uint2*)&sXh[row * XS + 2 * q] = make_uint2(pkbf(hx, hy), pkbf(hz, hw));
            }
        }
        PAIR_BAR(barid);   // barC: merge(sXl) + szb reads complete

        if (nv) {
            #pragma unroll
            for (int it = 0; it < 8; it++) {
                int idx = it * 64 + u;
                int row = r0 + (idx >> 5);
                int q   = idx & 31;
                float4 v = xp[it];
                float hx = __bfloat162float(__float2bfloat16(v.x));
                float hy = __bfloat162float(__float2bfloat16(v.y));
                float hz = __bfloat162float(__float2bfloat16(v.z));
                float hw = __bfloat162float(__float2bfloat16(v.w));
                *(uint2*)&sXl[row * XS + 2 * q] = make_uint2(pkbf(v.x - hx, v.y - hy),
                                                             pkbf(v.z - hz, v.w - hw));
            }
            int row = r0 + (u >> 2);
            int gn  = ntile * 128 + row;
            int gid = (gn < N) ? graph_id[gn] : 0;
            const float4* z4 = (const float4*)(g_zb + gid * 64);
            #pragma unroll
            for (int qq = 0; qq < 4; qq++) {
                int q = (u & 3) * 4 + qq;
                ((float4*)(szb + row * ZS))[q] = z4[q];
            }
        }
        PAIR_BAR(barid);   // barD: staging done before next L1
    }

    // ================= fused edge gather tail =================
    {
        const int units = (E + 7) >> 3;
        for (int iu = blockIdx.x * 512 + tid; iu < units; iu += gridDim.x * 512) {
            int e = iu * 8;
            if (e + 8 <= E) {
                int4 s0 = *(const int4*)(src + e);
                int4 s1 = *(const int4*)(src + e + 4);
                int4 d0 = *(const int4*)(dst + e);
                int4 d1 = *(const int4*)(dst + e + 4);
                int gs0 = graph_id[s0.x], gs1 = graph_id[s0.y], gs2 = graph_id[s0.z], gs3 = graph_id[s0.w];
                int gs4 = graph_id[s1.x], gs5 = graph_id[s1.y], gs6 = graph_id[s1.z], gs7 = graph_id[s1.w];
                int gd0 = graph_id[d0.x], gd1 = graph_id[d0.y], gd2 = graph_id[d0.z], gd3 = graph_id[d0.w];
                int gd4 = graph_id[d1.x], gd5 = graph_id[d1.y], gd6 = graph_id[d1.z], gd7 = graph_id[d1.w];
                float4 t0 = g_table[gs0 * MAXB + gd0];
                float4 t1 = g_table[gs1 * MAXB + gd1];
                float4 t2 = g_table[gs2 * MAXB + gd2];
                float4 t3 = g_table[gs3 * MAXB + gd3];
                float4 t4 = g_table[gs4 * MAXB + gd4];
                float4 t5 = g_table[gs5 * MAXB + gd5];
                float4 t6 = g_table[gs6 * MAXB + gd6];
                float4 t7 = g_table[gs7 * MAXB + gd7];
                float* o = out_edge + (size_t)e * 3;
                ((float4*)o)[0] = make_float4(t0.x, t0.y, t0.z, t1.x);
                ((float4*)o)[1] = make_float4(t1.y, t1.z, t2.x, t2.y);
                ((float4*)o)[2] = make_float4(t2.z, t3.x, t3.y, t3.z);
                ((float4*)o)[3] = make_float4(t4.x, t4.y, t4.z, t5.x);
                ((float4*)o)[4] = make_float4(t5.y, t5.z, t6.x, t6.y);
                ((float4*)o)[5] = make_float4(t6.z, t7.x, t7.y, t7.z);
            } else {
                for (int q = e; q < E; q++) {
                    float4 t = g_table[graph_id[src[q]] * MAXB + graph_id[dst[q]]];
                    out_edge[(size_t)q * 3 + 0] = t.x;
                    out_edge[(size_t)q * 3 + 1] = t.y;
                    out_edge[(size_t)q * 3 + 2] = t.z;
                }
            }
        }
    }
}

// ---------------------------------------------------------------------------
// Per-graph prep (nd1_b folded into g_zb)
// ---------------------------------------------------------------------------
__global__ void prep_kernel(const float* __restrict__ z,
                            const float* __restrict__ lp_w, const float* __restrict__ lp_b,
                            const float* __restrict__ nd1_w, const float* __restrict__ nd1_b,
                            const float* __restrict__ ed1_w,
                            const float* __restrict__ en1_w, const float* __restrict__ en1_b,
                            const float* __restrict__ en2_w, const float* __restrict__ en2_b,
                            const float* __restrict__ st1_w, const float* __restrict__ st1_b,
                            const float* __restrict__ st2_w, const float* __restrict__ st2_b,
                            float* __restrict__ out_energy, float* __restrict__ out_stress)
{
    const int b = blockIdx.x;
    const int t = threadIdx.x;
    __shared__ float zrow[32];
    __shared__ float zp[128];
    __shared__ float eh[64], sh[64];

    if (t < 32) zrow[t] = z[b * 32 + t];
    __syncthreads();
    {
        float acc = lp_b[t];
        #pragma unroll
        for (int k = 0; k < 32; k++) acc = fmaf(zrow[k], lp_w[k * 128 + t], acc);
        zp[t] = fmaxf(acc, 0.f);
    }
    if (t < 64) {
        float a1 = en1_b[t], a2 = st1_b[t];
        #pragma unroll
        for (int k = 0; k < 32; k++) {
            float zv = zrow[k];
            a1 = fmaf(zv, en1_w[k * 64 + t], a1);
            a2 = fmaf(zv, st1_w[k * 64 + t], a2);
        }
        eh[t] = fmaxf(a1, 0.f);
        sh[t] = fmaxf(a2, 0.f);
    }
    __syncthreads();
    if (t < 64) {
        float as = 0.f, bd = 0.f, zb = nd1_b[t];
        #pragma unroll 4
        for (int k = 0; k < 128; k++) {
            float zv = zp[k];
            as = fmaf(zv, ed1_w[k * 64 + t], as);
            bd = fmaf(zv, ed1_w[(128 + k) * 64 + t], bd);
            zb = fmaf(zv, nd1_w[k * 64 + t], zb);
        }
        g_As[b * 64 + t] = as;
        g_Bd[b * 64 + t] = bd;
        g_zb[b * 64 + t] = zb;
    }
    if (t < 2) {
        float a = en2_b[t];
        #pragma unroll 8
        for (int k = 0; k < 64; k++) a = fmaf(eh[k], en2_w[k * 2 + t], a);
        out_energy[b * 2 + t] = a;
    }
    if (t >= 16 && t < 25) {
        int j = t - 16;
        float a = st2_b[j];
        #pragma unroll 8
        for (int k = 0; k < 64; k++) a = fmaf(sh[k], st2_w[k * 9 + j], a);
        out_stress[b * 9 + j] = a;
    }
}

// ---------------------------------------------------------------------------
// Edge table (unchanged)
// ---------------------------------------------------------------------------
__global__ void edge_table_kernel(const float* __restrict__ ed1_b,
                                  const float* __restrict__ ed2_w,
                                  const float* __restrict__ ed2_b)
{
    const int gs = blockIdx.x;
    const int gd = threadIdx.x;
    __shared__ float sAs[64], sb1[64], sw2[64 * 3], sb2[3];
    const int t = threadIdx.x;
    if (t < 64) { sAs[t] = g_As[gs * 64 + t]; sb1[t] = ed1_b[t]; }
    if (t >= 64 && t < 64 + 192) sw2[t - 64] = ed2_w[t - 64];
    if (t < 3) sb2[t] = ed2_b[t];
    __syncthreads();

    float o0 = sb2[0], o1 = sb2[1], o2 = sb2[2];
    const float4* bd4 = (const float4*)(&g_Bd[gd * 64]);
    #pragma unroll
    for (int k4 = 0; k4 < 16; k4++) {
        float4 bv = bd4[k4];
        int k = k4 * 4;
        float h;
        h = fmaxf(sAs[k + 0] + bv.x + sb1[k + 0], 0.f);
        o0 = fmaf(h, sw2[(k + 0) * 3 + 0], o0); o1 = fmaf(h, sw2[(k + 0) * 3 + 1], o1); o2 = fmaf(h, sw2[(k + 0) * 3 + 2], o2);
        h = fmaxf(sAs[k + 1] + bv.y + sb1[k + 1], 0.f);
        o0 = fmaf(h, sw2[(k + 1) * 3 + 0], o0); o1 = fmaf(h, sw2[(k + 1) * 3 + 1], o1); o2 = fmaf(h, sw2[(k + 1) * 3 + 2], o2);
        h = fmaxf(sAs[k + 2] + bv.z + sb1[k + 2], 0.f);
        o0 = fmaf(h, sw2[(k + 2) * 3 + 0], o0); o1 = fmaf(h, sw2[(k + 2) * 3 + 1], o1); o2 = fmaf(h, sw2[(k + 2) * 3 + 2], o2);
        h = fmaxf(sAs[k + 3] + bv.w + sb1[k + 3], 0.f);
        o0 = fmaf(h, sw2[(k + 3) * 3 + 0], o0); o1 = fmaf(h, sw2[(k + 3) * 3 + 1], o1); o2 = fmaf(h, sw2[(k + 3) * 3 + 2], o2);
    }
    g_table[gs * MAXB + gd] = make_float4(o0, o1, o2, 0.f);
}

// ---------------------------------------------------------------------------
extern "C" void kernel_launch(void* const* d_in, const int* in_sizes, int n_in,
                              void* d_out, int out_size)
{
    const float* z        = (const float*)d_in[0];
    const float* node_emb = (const float*)d_in[1];
    const int*   graph_id = (const int*)  d_in[2];
    const int*   src      = (const int*)  d_in[3];
    const int*   dst      = (const int*)  d_in[4];
    const float* lp_w  = (const float*)d_in[5];
    const float* lp_b  = (const float*)d_in[6];
    const float* nep_w = (const float*)d_in[7];
    const float* nep_b = (const float*)d_in[8];
    const float* nd1_w = (const float*)d_in[9];
    const float* nd1_b = (const float*)d_in[10];
    const float* nd2_w = (const float*)d_in[11];
    const float* nd2_b = (const float*)d_in[12];
    const float* ed1_w = (const float*)d_in[13];
    const float* ed1_b = (const float*)d_in[14];
    const float* ed2_w = (const float*)d_in[15];
    const float* ed2_b = (const float*)d_in[16];
    const float* en1_w = (const float*)d_in[17];
    const float* en1_b = (const float*)d_in[18];
    const float* en2_w = (const float*)d_in[19];
    const float* en2_b = (const float*)d_in[20];
    const float* st1_w = (const float*)d_in[21];
    const float* st1_b = (const float*)d_in[22];
    const float* st2_w = (const float*)d_in[23];
    const float* st2_b = (const float*)d_in[24];

    const int B = in_sizes[0] / 32;
    const int N = in_sizes[1] / 128;
    const int E = in_sizes[3];

    float* out        = (float*)d_out;
    float* out_node   = out;
    float* out_edge   = out + (size_t)N * 4;
    float* out_energy = out + (size_t)N * 4 + (size_t)E * 3;
    float* out_stress = out_energy + (size_t)B * 2;

    cudaFuncSetAttribute(node_mma_kernel, cudaFuncAttributeMaxDynamicSharedMemorySize,
                         NODE_SMEM_BYTES);

    wconv_kernel<<<24, 256>>>(nep_w, nd1_w);

    prep_kernel<<<B, 128>>>(z, lp_w, lp_b, nd1_w, nd1_b, ed1_w,
                            en1_w, en1_b, en2_w, en2_b,
                            st1_w, st1_b, st2_w, st2_b,
                            out_energy, out_stress);

    edge_table_kernel<<<B, 256>>>(ed1_b, ed2_w, ed2_b);

    const int ntiles = (N + 127) / 128;
    const int grid = ntiles < 148 ? ntiles : 148;
    node_mma_kernel<<<grid, 512, NODE_SMEM_BYTES>>>(node_emb, graph_id,
                                                    nep_b, nd2_w, nd2_b,
                                                    out_node, N, ntiles,
                                                    src, dst, out_edge, E);
}

// round 7
// speedup vs baseline: 1.0684x; 1.0684x over previous
#include <cuda_runtime.h>
#include <cuda_bf16.h>
#include <cstdint>

// ---------------------------------------------------------------------------
// CrystalDecoder on GB300 (sm_103a via compute_103 PTX -> HMMA mma.sync only)
// Node path: 16-warp pair-autonomous bf16 hi/lo compensated mma.sync GEMM,
//            register zb loads, balanced split epilogue, truncation splits.
// Edge path: algebraic collapse to 256x256 lookup table + gather.
// ---------------------------------------------------------------------------

#define MAXB 256

__device__ float  g_zb[MAXB * 64];      // z_proj @ nd1_w + nd1_b
__device__ float  g_As[MAXB * 64];
__device__ float  g_Bd[MAXB * 64];
__device__ float4 g_table[MAXB * MAXB];

// transposed weights, bf16 hi/lo: W1^T [128 n][128 k], W2^T [64 n][128 k]
__device__ uint16_t g_w1thi[128 * 128];
__device__ uint16_t g_w1tlo[128 * 128];
__device__ uint16_t g_w2thi[64 * 128];
__device__ uint16_t g_w2tlo[64 * 128];

// u32 stride 68: (68*g + 8s + tg) mod 32 = (4g+tg) -> perfect bank permutation
#define XS 68

#define MMA16816(c, a, b0, b1) \
    asm volatile("mma.sync.aligned.m16n8k16.row.col.f32.bf16.bf16.f32 " \
        "{%0,%1,%2,%3}, {%4,%5,%6,%7}, {%8,%9}, {%0,%1,%2,%3};" \
        : "+f"((c)[0]), "+f"((c)[1]), "+f"((c)[2]), "+f"((c)[3]) \
        : "r"((a)[0]), "r"((a)[1]), "r"((a)[2]), "r"((a)[3]), "r"(b0), "r"(b1))

#define PAIR_BAR(id) asm volatile("bar.sync %0, 64;" :: "r"(id) : "memory")

__device__ __forceinline__ uint32_t pkbf(float a, float b) {
    __nv_bfloat162 t = __floats2bfloat162_rn(a, b);
    return *(uint32_t*)&t;
}

// truncation hi/lo split: hi = top-16 bits (exact bf16), lo = rn(x - hi)
__device__ __forceinline__ void tsplit2(float x0, float x1, uint32_t& hi, uint32_t& lo) {
    uint32_t u0 = __float_as_uint(x0), u1 = __float_as_uint(x1);
    hi = __byte_perm(u0, u1, 0x7632);
    float h0 = __uint_as_float(u0 & 0xFFFF0000u);
    float h1 = __uint_as_float(u1 & 0xFFFF0000u);
    float l0 = x0 - h0, l1 = x1 - h1;
    asm("cvt.rn.bf16x2.f32 %0, %1, %2;" : "=r"(lo) : "f"(l1), "f"(l0));
}

// ---------------------------------------------------------------------------
// Fused prep + weight conversion. Blocks [0,B): per-graph prep.
// Blocks [B, B+48): weight conversion (6144 threads strided).
// ---------------------------------------------------------------------------
__global__ void prep_wconv_kernel(const float* __restrict__ z,
                            const float* __restrict__ lp_w, const float* __restrict__ lp_b,
                            const float* __restrict__ nd1_w, const float* __restrict__ nd1_b,
                            const float* __restrict__ ed1_w,
                            const float* __restrict__ en1_w, const float* __restrict__ en1_b,
                            const float* __restrict__ en2_w, const float* __restrict__ en2_b,
                            const float* __restrict__ st1_w, const float* __restrict__ st1_b,
                            const float* __restrict__ st2_w, const float* __restrict__ st2_b,
                            const float* __restrict__ nep_w,
                            float* __restrict__ out_energy, float* __restrict__ out_stress,
                            int B)
{
    const int t = threadIdx.x;
    if (blockIdx.x >= B) {
        // ---- weight conversion ----
        int j0 = (blockIdx.x - B) * 128 + t;        // 0..6143
        for (int i = j0; i < 128 * 128; i += 6144) {
            int k = i >> 7, n = i & 127;
            float v = nep_w[k * 128 + n];
            __nv_bfloat16 hh = __float2bfloat16(v);
            __nv_bfloat16 ll = __float2bfloat16(v - __bfloat162float(hh));
            g_w1thi[n * 128 + k] = *(uint16_t*)&hh;
            g_w1tlo[n * 128 + k] = *(uint16_t*)&ll;
        }
        for (int i = j0; i < 64 * 128; i += 6144) {
            int k = i >> 6, n = i & 63;
            float v = nd1_w[k * 64 + n];
            __nv_bfloat16 hh = __float2bfloat16(v);
            __nv_bfloat16 ll = __float2bfloat16(v - __bfloat162float(hh));
            g_w2thi[n * 128 + k] = *(uint16_t*)&hh;
            g_w2tlo[n * 128 + k] = *(uint16_t*)&ll;
        }
        return;
    }

    const int b = blockIdx.x;
    __shared__ float zrow[32];
    __shared__ float zp[128];
    __shared__ float eh[64], sh[64];

    if (t < 32) zrow[t] = z[b * 32 + t];
    __syncthreads();
    {
        float acc = lp_b[t];
        #pragma unroll
        for (int k = 0; k < 32; k++) acc = fmaf(zrow[k], lp_w[k * 128 + t], acc);
        zp[t] = fmaxf(acc, 0.f);
    }
    if (t < 64) {
        float a1 = en1_b[t], a2 = st1_b[t];
        #pragma unroll
        for (int k = 0; k < 32; k++) {
            float zv = zrow[k];
            a1 = fmaf(zv, en1_w[k * 64 + t], a1);
            a2 = fmaf(zv, st1_w[k * 64 + t], a2);
        }
        eh[t] = fmaxf(a1, 0.f);
        sh[t] = fmaxf(a2, 0.f);
    }
    __syncthreads();
    if (t < 64) {
        float as = 0.f, bd = 0.f, zb = nd1_b[t];
        #pragma unroll 4
        for (int k = 0; k < 128; k++) {
            float zv = zp[k];
            as = fmaf(zv, ed1_w[k * 64 + t], as);
            bd = fmaf(zv, ed1_w[(128 + k) * 64 + t], bd);
            zb = fmaf(zv, nd1_w[k * 64 + t], zb);
        }
        g_As[b * 64 + t] = as;
        g_Bd[b * 64 + t] = bd;
        g_zb[b * 64 + t] = zb;
    }
    if (t < 2) {
        float a = en2_b[t];
        #pragma unroll 8
        for (int k = 0; k < 64; k++) a = fmaf(eh[k], en2_w[k * 2 + t], a);
        out_energy[b * 2 + t] = a;
    }
    if (t >= 16 && t < 25) {
        int j = t - 16;
        float a = st2_b[j];
        #pragma unroll 8
        for (int k = 0; k < 64; k++) a = fmaf(sh[k], st2_w[k * 9 + j], a);
        out_stress[b * 9 + j] = a;
    }
}

// ---------------------------------------------------------------------------
// Persistent node kernel: 512 threads, 16 warps = 8 autonomous pairs.
// ---------------------------------------------------------------------------
#define NODE_SMEM_U32 (2*128*XS + 2*64*XS + 2*128*XS + 128 + 256)
#define NODE_SMEM_BYTES (NODE_SMEM_U32 * 4)

__global__ void __launch_bounds__(512, 1)
node_mma_kernel(const float* __restrict__ node_emb, const int* __restrict__ graph_id,
                const float* __restrict__ b1,
                const float* __restrict__ w3, const float* __restrict__ b3,
                float* __restrict__ out_node, int N, int ntiles)
{
    extern __shared__ uint32_t su[];
    uint32_t* sW1h = su;                        // [128][XS]
    uint32_t* sW1l = sW1h + 128 * XS;
    uint32_t* sW2h = sW1l + 128 * XS;           // [64][XS]
    uint32_t* sW2l = sW2h + 64 * XS;
    uint32_t* sXh  = sW2l + 64 * XS;            // [128][XS]
    uint32_t* sXl  = sXh + 128 * XS;            // [128][XS]; merge aliases pair rows
    float*    sB1  = (float*)(sXl + 128 * XS);  // [128]
    float*    sW3  = sB1 + 128;                 // [64][4]

    const int tid  = threadIdx.x;
    const int lane = tid & 31;
    const int w    = tid >> 5;       // 0..15
    const int p    = w >> 1;         // pair 0..7
    const int h    = w & 1;          // half
    const int g    = lane >> 2;
    const int tg   = lane & 3;
    const int r0   = p * 16;
    const int u    = tid & 63;       // thread within pair
    const int barid = p + 1;
    const int myrow = r0 + g + (h ? 8 : 0);   // the row this warp finalizes
    float* mrg = (float*)(sXl + p * 1088);    // 4KB inside own pair's sXl rows
    // layout: h0 partials [0..511], h1 partials [512..1023]

    // ---- one-time staging (block-wide) ----
    for (int i = tid; i < 128 * 64; i += 512) {
        int n = i >> 6, kp = i & 63;
        sW1h[n * XS + kp] = ((const uint32_t*)g_w1thi)[i];
        sW1l[n * XS + kp] = ((const uint32_t*)g_w1tlo)[i];
    }
    for (int i = tid; i < 64 * 64; i += 512) {
        int n = i >> 6, kp = i & 63;
        sW2h[n * XS + kp] = ((const uint32_t*)g_w2thi)[i];
        sW2l[n * XS + kp] = ((const uint32_t*)g_w2tlo)[i];
    }
    if (tid < 128) sB1[tid] = b1[tid];
    else if (tid >= 256 && tid < 320) ((float4*)sW3)[tid - 256] = ((const float4*)w3)[tid - 256];
    const float b30 = b3[0], b31 = b3[1], b32 = b3[2], b33 = b3[3];

    // ---- prologue: stage tile0 (pair-local rows only) ----
    int tile = blockIdx.x;
    if (tile < ntiles) {
        const int base = tile * 128;
        #pragma unroll
        for (int it = 0; it < 8; it++) {
            int idx = it * 64 + u;
            int row = r0 + (idx >> 5);
            int q   = idx & 31;
            int gn  = base + row;
            float4 v = (gn < N) ? ((const float4*)(node_emb + (size_t)gn * 128))[q]
                                : make_float4(0.f, 0.f, 0.f, 0.f);
            uint32_t h0v, l0v, h1v, l1v;
            tsplit2(v.x, v.y, h0v, l0v);
            tsplit2(v.z, v.w, h1v, l1v);
            *(uint2*)&sXh[row * XS + 2 * q] = make_uint2(h0v, h1v);
            *(uint2*)&sXl[row * XS + 2 * q] = make_uint2(l0v, l1v);
        }
    }
    __syncthreads();   // only block-wide sync

    for (; tile < ntiles; tile += gridDim.x) {
        const int base = tile * 128;
        const int grow = base + myrow;
        // gid for this warp's output row (latency hidden by L1)
        const int gid = graph_id[(grow < N) ? grow : (N - 1)];

        // ---- Layer 1: 8 n-tiles (global nt = 8h+j), all 8 k-steps ----
        float acc[8][4];
        #pragma unroll
        for (int j = 0; j < 8; j++)
            #pragma unroll
            for (int q = 0; q < 4; q++) acc[j][q] = 0.f;

        const uint32_t* xh0 = &sXh[(r0 + g) * XS];
        const uint32_t* xh1 = &sXh[(r0 + g + 8) * XS];
        const uint32_t* xl0 = &sXl[(r0 + g) * XS];
        const uint32_t* xl1 = &sXl[(r0 + g + 8) * XS];

        #pragma unroll
        for (int s = 0; s < 8; s++) {
            const int o = s * 8 + tg;
            uint32_t aH[4] = { xh0[o], xh1[o], xh0[o + 4], xh1[o + 4] };
            uint32_t aL[4] = { xl0[o], xl1[o], xl0[o + 4], xl1[o + 4] };
            #pragma unroll
            for (int j = 0; j < 8; j++) {
                const int nrow = ((8 * h + j) * 8 + g) * XS;
                uint32_t bh0 = sW1h[nrow + o], bh1 = sW1h[nrow + o + 4];
                uint32_t bl0 = sW1l[nrow + o], bl1 = sW1l[nrow + o + 4];
                MMA16816(acc[j], aH, bh0, bh1);
                MMA16816(acc[j], aH, bl0, bl1);
                MMA16816(acc[j], aL, bh0, bh1);
            }
        }
        PAIR_BAR(barid);   // barA: pair done reading its sX rows

        // ---- prefetch next tile's X into registers ----
        const int  ntile = tile + gridDim.x;
        const bool nv    = ntile < ntiles;
        float4 xp[8];
        if (nv) {
            const int nbase = ntile * 128;
            #pragma unroll
            for (int it = 0; it < 8; it++) {
                int idx = it * 64 + u;
                int row = r0 + (idx >> 5);
                int q   = idx & 31;
                int gn  = nbase + row;
                xp[it] = (gn < N) ? ((const float4*)(node_emb + (size_t)gn * 128))[q]
                                  : make_float4(0.f, 0.f, 0.f, 0.f);
            }
        }

        // ---- epilogue 1 (registers): bias+relu, truncation split -> A2 ----
        uint32_t a2h[4][4], a2l[4][4];
        #pragma unroll
        for (int s2 = 0; s2 < 4; s2++) {
            int cA = (4 * h + s2) * 16 + tg * 2;
            int cB = cA + 8;
            float bA0 = sB1[cA], bA1 = sB1[cA + 1];
            float bB0 = sB1[cB], bB1 = sB1[cB + 1];
            tsplit2(fmaxf(acc[2 * s2][0] + bA0, 0.f),
                    fmaxf(acc[2 * s2][1] + bA1, 0.f), a2h[s2][0], a2l[s2][0]);
            tsplit2(fmaxf(acc[2 * s2][2] + bA0, 0.f),
                    fmaxf(acc[2 * s2][3] + bA1, 0.f), a2h[s2][1], a2l[s2][1]);
            tsplit2(fmaxf(acc[2 * s2 + 1][0] + bB0, 0.f),
                    fmaxf(acc[2 * s2 + 1][1] + bB1, 0.f), a2h[s2][2], a2l[s2][2]);
            tsplit2(fmaxf(acc[2 * s2 + 1][2] + bB0, 0.f),
                    fmaxf(acc[2 * s2 + 1][3] + bB1, 0.f), a2h[s2][3], a2l[s2][3]);
        }

        // ---- Layer 2: all 8 n-tiles, local k-half (4 steps) -> partial ----
        float acc2[8][4];
        #pragma unroll
        for (int j = 0; j < 8; j++)
            #pragma unroll
            for (int q = 0; q < 4; q++) acc2[j][q] = 0.f;

        #pragma unroll
        for (int s = 0; s < 4; s++) {
            const int o = (4 * h + s) * 8 + tg;
            #pragma unroll
            for (int j = 0; j < 8; j++) {
                const int nrow = (j * 8 + g) * XS;
                uint32_t bh0 = sW2h[nrow + o], bh1 = sW2h[nrow + o + 4];
                uint32_t bl0 = sW2l[nrow + o], bl1 = sW2l[nrow + o + 4];
                MMA16816(acc2[j], a2h[s], bh0, bh1);
                MMA16816(acc2[j], a2h[s], bl0, bl1);
                MMA16816(acc2[j], a2l[s], bh0, bh1);
            }
        }

        // ---- zb prefetch for this warp's row (L2 hit, hidden by merge) ----
        float2 zbv[8];
        {
            const float2* zp2 = (const float2*)(g_zb + gid * 64);
            #pragma unroll
            for (int nt = 0; nt < 8; nt++) zbv[nt] = zp2[nt * 4 + tg];
        }

        // ---- balanced merge: h0 stores rB-half, h1 stores rA-half ----
        {
            float* dstp = mrg + (h ? 512 : 0);
            int qo = h ? 0 : 2;
            #pragma unroll
            for (int j = 0; j < 8; j++) {
                dstp[(j * 2 + 0) * 32 + lane] = acc2[j][qo + 0];
                dstp[(j * 2 + 1) * 32 + lane] = acc2[j][qo + 1];
            }
        }
        PAIR_BAR(barid);   // barB

        // ---- each warp finalizes its own row (rA for h0, rB for h1) ----
        {
            const float* srcp = mrg + (h ? 0 : 512);
            int qo = h ? 2 : 0;
            float o0 = 0.f, o1 = 0.f, o2 = 0.f, o3 = 0.f;
            #pragma unroll
            for (int nt = 0; nt < 8; nt++) {
                float v0 = acc2[nt][qo + 0] + srcp[(nt * 2 + 0) * 32 + lane];
                float v1 = acc2[nt][qo + 1] + srcp[(nt * 2 + 1) * 32 + lane];
                float hv0 = fmaxf(v0 + zbv[nt].x, 0.f);
                float hv1 = fmaxf(v1 + zbv[nt].y, 0.f);
                int c0 = nt * 8 + tg * 2;
                float4 w0 = *(const float4*)&sW3[c0 * 4];
                float4 w1 = *(const float4*)&sW3[(c0 + 1) * 4];
                o0 = fmaf(hv0, w0.x, fmaf(hv1, w1.x, o0));
                o1 = fmaf(hv0, w0.y, fmaf(hv1, w1.y, o1));
                o2 = fmaf(hv0, w0.z, fmaf(hv1, w1.z, o2));
                o3 = fmaf(hv0, w0.w, fmaf(hv1, w1.w, o3));
            }
            #pragma unroll
            for (int d = 1; d <= 2; d <<= 1) {
                o0 += __shfl_xor_sync(0xFFFFFFFF, o0, d);
                o1 += __shfl_xor_sync(0xFFFFFFFF, o1, d);
                o2 += __shfl_xor_sync(0xFFFFFFFF, o2, d);
                o3 += __shfl_xor_sync(0xFFFFFFFF, o3, d);
            }
            if (tg == 0 && grow < N)
                *(float4*)&out_node[(size_t)grow * 4] =
                    make_float4(o0 + b30, o1 + b31, o2 + b32, o3 + b33);
        }

        // ---- write next X hi (sXh dead since barA; pair-local rows) ----
        if (nv) {
            #pragma unroll
            for (int it = 0; it < 8; it++) {
                int idx = it * 64 + u;
                int row = r0 + (idx >> 5);
                int q   = idx & 31;
                float4 v = xp[it];
                uint32_t h0v, l0v, h1v, l1v;
                tsplit2(v.x, v.y, h0v, l0v);
                tsplit2(v.z, v.w, h1v, l1v);
                *(uint2*)&sXh[row * XS + 2 * q] = make_uint2(h0v, h1v);
            }
        }
        PAIR_BAR(barid);   // barC: both warps' merge reads complete

        if (nv) {
            #pragma unroll
            for (int it = 0; it < 8; it++) {
                int idx = it * 64 + u;
                int row = r0 + (idx >> 5);
                int q   = idx & 31;
                float4 v = xp[it];
                uint32_t h0v, l0v, h1v, l1v;
                tsplit2(v.x, v.y, h0v, l0v);
                tsplit2(v.z, v.w, h1v, l1v);
                *(uint2*)&sXl[row * XS + 2 * q] = make_uint2(l0v, l1v);
            }
        }
        PAIR_BAR(barid);   // barD: staging done before next L1
    }
}

// ---------------------------------------------------------------------------
// Edge table (unchanged)
// ---------------------------------------------------------------------------
__global__ void edge_table_kernel(const float* __restrict__ ed1_b,
                                  const float* __restrict__ ed2_w,
                                  const float* __restrict__ ed2_b)
{
    const int gs = blockIdx.x;
    const int gd = threadIdx.x;
    __shared__ float sAs[64], sb1[64], sw2[64 * 3], sb2[3];
    const int t = threadIdx.x;
    if (t < 64) { sAs[t] = g_As[gs * 64 + t]; sb1[t] = ed1_b[t]; }
    if (t >= 64 && t < 64 + 192) sw2[t - 64] = ed2_w[t - 64];
    if (t < 3) sb2[t] = ed2_b[t];
    __syncthreads();

    float o0 = sb2[0], o1 = sb2[1], o2 = sb2[2];
    const float4* bd4 = (const float4*)(&g_Bd[gd * 64]);
    #pragma unroll
    for (int k4 = 0; k4 < 16; k4++) {
        float4 bv = bd4[k4];
        int k = k4 * 4;
        float h;
        h = fmaxf(sAs[k + 0] + bv.x + sb1[k + 0], 0.f);
        o0 = fmaf(h, sw2[(k + 0) * 3 + 0], o0); o1 = fmaf(h, sw2[(k + 0) * 3 + 1], o1); o2 = fmaf(h, sw2[(k + 0) * 3 + 2], o2);
        h = fmaxf(sAs[k + 1] + bv.y + sb1[k + 1], 0.f);
        o0 = fmaf(h, sw2[(k + 1) * 3 + 0], o0); o1 = fmaf(h, sw2[(k + 1) * 3 + 1], o1); o2 = fmaf(h, sw2[(k + 1) * 3 + 2], o2);
        h = fmaxf(sAs[k + 2] + bv.z + sb1[k + 2], 0.f);
        o0 = fmaf(h, sw2[(k + 2) * 3 + 0], o0); o1 = fmaf(h, sw2[(k + 2) * 3 + 1], o1); o2 = fmaf(h, sw2[(k + 2) * 3 + 2], o2);
        h = fmaxf(sAs[k + 3] + bv.w + sb1[k + 3], 0.f);
        o0 = fmaf(h, sw2[(k + 3) * 3 + 0], o0); o1 = fmaf(h, sw2[(k + 3) * 3 + 1], o1); o2 = fmaf(h, sw2[(k + 3) * 3 + 2], o2);
    }
    g_table[gs * MAXB + gd] = make_float4(o0, o1, o2, 0.f);
}

// ---------------------------------------------------------------------------
// Edge gather: 8 edges/thread, batched independent loads (standalone, high occ)
// ---------------------------------------------------------------------------
__global__ void edge_gather_kernel(const int* __restrict__ src, const int* __restrict__ dst,
                                   const int* __restrict__ graph_id,
                                   float* __restrict__ out_edge, int E)
{
    int e = (blockIdx.x * blockDim.x + threadIdx.x) * 8;
    if (e >= E) return;
    if (e + 8 <= E) {
        int4 s0 = *(const int4*)(src + e);
        int4 s1 = *(const int4*)(src + e + 4);
        int4 d0 = *(const int4*)(dst + e);
        int4 d1 = *(const int4*)(dst + e + 4);
        int gs0 = graph_id[s0.x], gs1 = graph_id[s0.y], gs2 = graph_id[s0.z], gs3 = graph_id[s0.w];
        int gs4 = graph_id[s1.x], gs5 = graph_id[s1.y], gs6 = graph_id[s1.z], gs7 = graph_id[s1.w];
        int gd0 = graph_id[d0.x], gd1 = graph_id[d0.y], gd2 = graph_id[d0.z], gd3 = graph_id[d0.w];
        int gd4 = graph_id[d1.x], gd5 = graph_id[d1.y], gd6 = graph_id[d1.z], gd7 = graph_id[d1.w];
        float4 t0 = g_table[gs0 * MAXB + gd0];
        float4 t1 = g_table[gs1 * MAXB + gd1];
        float4 t2 = g_table[gs2 * MAXB + gd2];
        float4 t3 = g_table[gs3 * MAXB + gd3];
        float4 t4 = g_table[gs4 * MAXB + gd4];
        float4 t5 = g_table[gs5 * MAXB + gd5];
        float4 t6 = g_table[gs6 * MAXB + gd6];
        float4 t7 = g_table[gs7 * MAXB + gd7];
        float* o = out_edge + (size_t)e * 3;
        ((float4*)o)[0] = make_float4(t0.x, t0.y, t0.z, t1.x);
        ((float4*)o)[1] = make_float4(t1.y, t1.z, t2.x, t2.y);
        ((float4*)o)[2] = make_float4(t2.z, t3.x, t3.y, t3.z);
        ((float4*)o)[3] = make_float4(t4.x, t4.y, t4.z, t5.x);
        ((float4*)o)[4] = make_float4(t5.y, t5.z, t6.x, t6.y);
        ((float4*)o)[5] = make_float4(t6.z, t7.x, t7.y, t7.z);
    } else {
        for (int q = e; q < E; q++) {
            float4 t = g_table[graph_id[src[q]] * MAXB + graph_id[dst[q]]];
            out_edge[(size_t)q * 3 + 0] = t.x;
            out_edge[(size_t)q * 3 + 1] = t.y;
            out_edge[(size_t)q * 3 + 2] = t.z;
        }
    }
}

// ---------------------------------------------------------------------------
extern "C" void kernel_launch(void* const* d_in, const int* in_sizes, int n_in,
                              void* d_out, int out_size)
{
    const float* z        = (const float*)d_in[0];
    const float* node_emb = (const float*)d_in[1];
    const int*   graph_id = (const int*)  d_in[2];
    const int*   src      = (const int*)  d_in[3];
    const int*   dst      = (const int*)  d_in[4];
    const float* lp_w  = (const float*)d_in[5];
    const float* lp_b  = (const float*)d_in[6];
    const float* nep_w = (const float*)d_in[7];
    const float* nep_b = (const float*)d_in[8];
    const float* nd1_w = (const float*)d_in[9];
    const float* nd1_b = (const float*)d_in[10];
    const float* nd2_w = (const float*)d_in[11];
    const float* nd2_b = (const float*)d_in[12];
    const float* ed1_w = (const float*)d_in[13];
    const float* ed1_b = (const float*)d_in[14];
    const float* ed2_w = (const float*)d_in[15];
    const float* ed2_b = (const float*)d_in[16];
    const float* en1_w = (const float*)d_in[17];
    const float* en1_b = (const float*)d_in[18];
    const float* en2_w = (const float*)d_in[19];
    const float* en2_b = (const float*)d_in[20];
    const float* st1_w = (const float*)d_in[21];
    const float* st1_b = (const float*)d_in[22];
    const float* st2_w = (const float*)d_in[23];
    const float* st2_b = (const float*)d_in[24];

    const int B = in_sizes[0] / 32;
    const int N = in_sizes[1] / 128;
    const int E = in_sizes[3];

    float* out        = (float*)d_out;
    float* out_node   = out;
    float* out_edge   = out + (size_t)N * 4;
    float* out_energy = out + (size_t)N * 4 + (size_t)E * 3;
    float* out_stress = out_energy + (size_t)B * 2;

    cudaFuncSetAttribute(node_mma_kernel, cudaFuncAttributeMaxDynamicSharedMemorySize,
                         NODE_SMEM_BYTES);

    prep_wconv_kernel<<<B + 48, 128>>>(z, lp_w, lp_b, nd1_w, nd1_b, ed1_w,
                                       en1_w, en1_b, en2_w, en2_b,
                                       st1_w, st1_b, st2_w, st2_b,
                                       nep_w, out_energy, out_stress, B);

    edge_table_kernel<<<B, 256>>>(ed1_b, ed2_w, ed2_b);

    const int ntiles = (N + 127) / 128;
    const int grid = ntiles < 148 ? ntiles : 148;
    node_mma_kernel<<<grid, 512, NODE_SMEM_BYTES>>>(node_emb, graph_id,
                                                    nep_b, nd2_w, nd2_b,
                                                    out_node, N, ntiles);

    const int eth = (E + 7) / 8;
    edge_gather_kernel<<<(eth + 255) / 256, 256>>>(src, dst, graph_id, out_edge, E);
}

// round 8
// speedup vs baseline: 1.0841x; 1.0146x over previous
#include <cuda_runtime.h>
#include <cuda_bf16.h>
#include <cstdint>

// ---------------------------------------------------------------------------
// CrystalDecoder on GB300 (sm_103a via compute_103 PTX -> HMMA mma.sync only)
// Node path: 16-warp pair-autonomous compensated mma.sync GEMM with a dynamic
//            pair-level work queue (atomic ticket).
// Edge path: 256x256 lookup table + uint8-gid gather (L1-resident index).
// ---------------------------------------------------------------------------

#define MAXB 256

__device__ float  g_zb[MAXB * 64];      // z_proj @ nd1_w + nd1_b
__device__ float  g_As[MAXB * 64];
__device__ float  g_Bd[MAXB * 64];
__device__ float4 g_table[MAXB * MAXB];
__device__ int    g_ctr;                // dynamic work-queue ticket
__device__ uint8_t g_gid8[262144];      // uint8 graph_id (fits L1)

// transposed weights, bf16 hi/lo: W1^T [128 n][128 k], W2^T [64 n][128 k]
__device__ uint16_t g_w1thi[128 * 128];
__device__ uint16_t g_w1tlo[128 * 128];
__device__ uint16_t g_w2thi[64 * 128];
__device__ uint16_t g_w2tlo[64 * 128];

#define XS 68
#define NODE_GRID 148
#define NPAIRS (NODE_GRID * 8)

#define MMA16816(c, a, b0, b1) \
    asm volatile("mma.sync.aligned.m16n8k16.row.col.f32.bf16.bf16.f32 " \
        "{%0,%1,%2,%3}, {%4,%5,%6,%7}, {%8,%9}, {%0,%1,%2,%3};" \
        : "+f"((c)[0]), "+f"((c)[1]), "+f"((c)[2]), "+f"((c)[3]) \
        : "r"((a)[0]), "r"((a)[1]), "r"((a)[2]), "r"((a)[3]), "r"(b0), "r"(b1))

#define PAIR_BAR(id) asm volatile("bar.sync %0, 64;" :: "r"(id) : "memory")

// truncation hi/lo split: hi = top-16 bits (exact bf16), lo = rn(x - hi)
__device__ __forceinline__ void tsplit2(float x0, float x1, uint32_t& hi, uint32_t& lo) {
    uint32_t u0 = __float_as_uint(x0), u1 = __float_as_uint(x1);
    hi = __byte_perm(u0, u1, 0x7632);
    float h0 = __uint_as_float(u0 & 0xFFFF0000u);
    float h1 = __uint_as_float(u1 & 0xFFFF0000u);
    float l0 = x0 - h0, l1 = x1 - h1;
    asm("cvt.rn.bf16x2.f32 %0, %1, %2;" : "=r"(lo) : "f"(l1), "f"(l0));
}

// ---------------------------------------------------------------------------
// Fused prep + weight conversion + gid8 + queue reset.
// Blocks [0,B): per-graph prep. Blocks [B, B+48): conversion work.
// ---------------------------------------------------------------------------
__global__ void prep_wconv_kernel(const float* __restrict__ z,
                            const float* __restrict__ lp_w, const float* __restrict__ lp_b,
                            const float* __restrict__ nd1_w, const float* __restrict__ nd1_b,
                            const float* __restrict__ ed1_w,
                            const float* __restrict__ en1_w, const float* __restrict__ en1_b,
                            const float* __restrict__ en2_w, const float* __restrict__ en2_b,
                            const float* __restrict__ st1_w, const float* __restrict__ st1_b,
                            const float* __restrict__ st2_w, const float* __restrict__ st2_b,
                            const float* __restrict__ nep_w,
                            const int* __restrict__ graph_id, int N,
                            float* __restrict__ out_energy, float* __restrict__ out_stress,
                            int B)
{
    const int t = threadIdx.x;
    if (blockIdx.x >= B) {
        int j0 = (blockIdx.x - B) * 128 + t;        // 0..6143
        if (blockIdx.x == B && t == 0) g_ctr = NPAIRS;
        for (int i = j0; i < 128 * 128; i += 6144) {
            int k = i >> 7, n = i & 127;
            float v = nep_w[k * 128 + n];
            __nv_bfloat16 hh = __float2bfloat16(v);
            __nv_bfloat16 ll = __float2bfloat16(v - __bfloat162float(hh));
            g_w1thi[n * 128 + k] = *(uint16_t*)&hh;
            g_w1tlo[n * 128 + k] = *(uint16_t*)&ll;
        }
        for (int i = j0; i < 64 * 128; i += 6144) {
            int k = i >> 6, n = i & 63;
            float v = nd1_w[k * 64 + n];
            __nv_bfloat16 hh = __float2bfloat16(v);
            __nv_bfloat16 ll = __float2bfloat16(v - __bfloat162float(hh));
            g_w2thi[n * 128 + k] = *(uint16_t*)&hh;
            g_w2tlo[n * 128 + k] = *(uint16_t*)&ll;
        }
        for (int i = j0; i < N; i += 6144)
            g_gid8[i] = (uint8_t)graph_id[i];
        return;
    }

    const int b = blockIdx.x;
    __shared__ float zrow[32];
    __shared__ float zp[128];
    __shared__ float eh[64], sh[64];

    if (t < 32) zrow[t] = z[b * 32 + t];
    __syncthreads();
    {
        float acc = lp_b[t];
        #pragma unroll
        for (int k = 0; k < 32; k++) acc = fmaf(zrow[k], lp_w[k * 128 + t], acc);
        zp[t] = fmaxf(acc, 0.f);
    }
    if (t < 64) {
        float a1 = en1_b[t], a2 = st1_b[t];
        #pragma unroll
        for (int k = 0; k < 32; k++) {
            float zv = zrow[k];
            a1 = fmaf(zv, en1_w[k * 64 + t], a1);
            a2 = fmaf(zv, st1_w[k * 64 + t], a2);
        }
        eh[t] = fmaxf(a1, 0.f);
        sh[t] = fmaxf(a2, 0.f);
    }
    __syncthreads();
    if (t < 64) {
        float as = 0.f, bd = 0.f, zb = nd1_b[t];
        #pragma unroll 4
        for (int k = 0; k < 128; k++) {
            float zv = zp[k];
            as = fmaf(zv, ed1_w[k * 64 + t], as);
            bd = fmaf(zv, ed1_w[(128 + k) * 64 + t], bd);
            zb = fmaf(zv, nd1_w[k * 64 + t], zb);
        }
        g_As[b * 64 + t] = as;
        g_Bd[b * 64 + t] = bd;
        g_zb[b * 64 + t] = zb;
    }
    if (t < 2) {
        float a = en2_b[t];
        #pragma unroll 8
        for (int k = 0; k < 64; k++) a = fmaf(eh[k], en2_w[k * 2 + t], a);
        out_energy[b * 2 + t] = a;
    }
    if (t >= 16 && t < 25) {
        int j = t - 16;
        float a = st2_b[j];
        #pragma unroll 8
        for (int k = 0; k < 64; k++) a = fmaf(sh[k], st2_w[k * 9 + j], a);
        out_stress[b * 9 + j] = a;
    }
}

// ---------------------------------------------------------------------------
// Persistent node kernel: 512 threads, 8 autonomous pairs, dynamic queue.
// Work unit = 16 node rows. U = ceil(N/16).
// ---------------------------------------------------------------------------
#define NODE_SMEM_U32 (2*128*XS + 2*64*XS + 2*128*XS + 128 + 256 + 8)
#define NODE_SMEM_BYTES (NODE_SMEM_U32 * 4)

__global__ void __launch_bounds__(512, 1)
node_mma_kernel(const float* __restrict__ node_emb, const int* __restrict__ graph_id,
                const float* __restrict__ b1,
                const float* __restrict__ w3, const float* __restrict__ b3,
                float* __restrict__ out_node, int N, int U)
{
    extern __shared__ uint32_t su[];
    uint32_t* sW1h = su;                        // [128][XS]
    uint32_t* sW1l = sW1h + 128 * XS;
    uint32_t* sW2h = sW1l + 128 * XS;           // [64][XS]
    uint32_t* sW2l = sW2h + 64 * XS;
    uint32_t* sXh  = sW2l + 64 * XS;            // [128][XS]
    uint32_t* sXl  = sXh + 128 * XS;            // [128][XS]; merge aliases pair rows
    float*    sB1  = (float*)(sXl + 128 * XS);  // [128]
    float*    sW3  = sB1 + 128;                 // [64][4]
    int*      sNU  = (int*)(sW3 + 256);         // [8] next-unit per pair

    const int tid  = threadIdx.x;
    const int lane = tid & 31;
    const int w    = tid >> 5;       // 0..15
    const int p    = w >> 1;         // pair 0..7
    const int h    = w & 1;          // half
    const int g    = lane >> 2;
    const int tg   = lane & 3;
    const int r0   = p * 16;
    const int u    = tid & 63;       // thread within pair
    const int barid = p + 1;
    const int rloc = g + (h ? 8 : 0);           // local row this warp finalizes
    float* mrg = (float*)(sXl + p * 1088);      // 4KB inside own pair's sXl rows

    // ---- one-time staging (block-wide) ----
    for (int i = tid; i < 128 * 64; i += 512) {
        int n = i >> 6, kp = i & 63;
        sW1h[n * XS + kp] = ((const uint32_t*)g_w1thi)[i];
        sW1l[n * XS + kp] = ((const uint32_t*)g_w1tlo)[i];
    }
    for (int i = tid; i < 64 * 64; i += 512) {
        int n = i >> 6, kp = i & 63;
        sW2h[n * XS + kp] = ((const uint32_t*)g_w2thi)[i];
        sW2l[n * XS + kp] = ((const uint32_t*)g_w2tlo)[i];
    }
    if (tid < 128) sB1[tid] = b1[tid];
    else if (tid >= 256 && tid < 320) ((float4*)sW3)[tid - 256] = ((const float4*)w3)[tid - 256];
    const float b30 = b3[0], b31 = b3[1], b32 = b3[2], b33 = b3[3];

    // ---- prologue: stage this pair's first unit ----
    int unit = blockIdx.x * 8 + p;
    if (unit < U) {
        const int gbase = unit * 16;
        #pragma unroll
        for (int it = 0; it < 8; it++) {
            int idx = it * 64 + u;
            int rl  = idx >> 5;              // 0..15
            int q   = idx & 31;
            int gn  = gbase + rl;
            float4 v = (gn < N) ? ((const float4*)(node_emb + (size_t)gn * 128))[q]
                                : make_float4(0.f, 0.f, 0.f, 0.f);
            uint32_t h0v, l0v, h1v, l1v;
            tsplit2(v.x, v.y, h0v, l0v);
            tsplit2(v.z, v.w, h1v, l1v);
            *(uint2*)&sXh[(r0 + rl) * XS + 2 * q] = make_uint2(h0v, h1v);
            *(uint2*)&sXl[(r0 + rl) * XS + 2 * q] = make_uint2(l0v, l1v);
        }
    }
    __syncthreads();   // only block-wide sync

    while (unit < U) {
        const int gbase = unit * 16;
        const int grow = gbase + rloc;
        const int gid = graph_id[(grow < N) ? grow : (N - 1)];

        // grab next unit early; latency hidden under L1 MMAs
        if (h == 0 && lane == 0) sNU[p] = atomicAdd(&g_ctr, 1);

        // ---- Layer 1: 8 n-tiles (global nt = 8h+j), all 8 k-steps ----
        float acc[8][4];
        #pragma unroll
        for (int j = 0; j < 8; j++)
            #pragma unroll
            for (int q = 0; q < 4; q++) acc[j][q] = 0.f;

        const uint32_t* xh0 = &sXh[(r0 + g) * XS];
        const uint32_t* xh1 = &sXh[(r0 + g + 8) * XS];
        const uint32_t* xl0 = &sXl[(r0 + g) * XS];
        const uint32_t* xl1 = &sXl[(r0 + g + 8) * XS];

        #pragma unroll
        for (int s = 0; s < 8; s++) {
            const int o = s * 8 + tg;
            uint32_t aH[4] = { xh0[o], xh1[o], xh0[o + 4], xh1[o + 4] };
            uint32_t aL[4] = { xl0[o], xl1[o], xl0[o + 4], xl1[o + 4] };
            #pragma unroll
            for (int j = 0; j < 8; j++) {
                const int nrow = ((8 * h + j) * 8 + g) * XS;
                uint32_t bh0 = sW1h[nrow + o], bh1 = sW1h[nrow + o + 4];
                uint32_t bl0 = sW1l[nrow + o], bl1 = sW1l[nrow + o + 4];
                MMA16816(acc[j], aH, bh0, bh1);
                MMA16816(acc[j], aH, bl0, bl1);
                MMA16816(acc[j], aL, bh0, bh1);
            }
        }
        PAIR_BAR(barid);   // barA: pair done reading its sX rows; sNU visible

        // ---- prefetch next unit's X into registers ----
        const int  nunit = sNU[p];
        const bool nv    = nunit < U;
        float4 xp[8];
        if (nv) {
            const int nbase = nunit * 16;
            #pragma unroll
            for (int it = 0; it < 8; it++) {
                int idx = it * 64 + u;
                int gn  = nbase + (idx >> 5);
                xp[it] = (gn < N) ? ((const float4*)(node_emb + (size_t)gn * 128))[idx & 31]
                                  : make_float4(0.f, 0.f, 0.f, 0.f);
            }
        }

        // ---- epilogue 1 (registers): bias+relu, truncation split -> A2 ----
        uint32_t a2h[4][4], a2l[4][4];
        #pragma unroll
        for (int s2 = 0; s2 < 4; s2++) {
            int cA = (4 * h + s2) * 16 + tg * 2;
            int cB = cA + 8;
            float bA0 = sB1[cA], bA1 = sB1[cA + 1];
            float bB0 = sB1[cB], bB1 = sB1[cB + 1];
            tsplit2(fmaxf(acc[2 * s2][0] + bA0, 0.f),
                    fmaxf(acc[2 * s2][1] + bA1, 0.f), a2h[s2][0], a2l[s2][0]);
            tsplit2(fmaxf(acc[2 * s2][2] + bA0, 0.f),
                    fmaxf(acc[2 * s2][3] + bA1, 0.f), a2h[s2][1], a2l[s2][1]);
            tsplit2(fmaxf(acc[2 * s2 + 1][0] + bB0, 0.f),
                    fmaxf(acc[2 * s2 + 1][1] + bB1, 0.f), a2h[s2][2], a2l[s2][2]);
            tsplit2(fmaxf(acc[2 * s2 + 1][2] + bB0, 0.f),
                    fmaxf(acc[2 * s2 + 1][3] + bB1, 0.f), a2h[s2][3], a2l[s2][3]);
        }

        // ---- Layer 2: all 8 n-tiles, local k-half (4 steps) -> partial ----
        float acc2[8][4];
        #pragma unroll
        for (int j = 0; j < 8; j++)
            #pragma unroll
            for (int q = 0; q < 4; q++) acc2[j][q] = 0.f;

        #pragma unroll
        for (int s = 0; s < 4; s++) {
            const int o = (4 * h + s) * 8 + tg;
            #pragma unroll
            for (int j = 0; j < 8; j++) {
                const int nrow = (j * 8 + g) * XS;
                uint32_t bh0 = sW2h[nrow + o], bh1 = sW2h[nrow + o + 4];
                uint32_t bl0 = sW2l[nrow + o], bl1 = sW2l[nrow + o + 4];
                MMA16816(acc2[j], a2h[s], bh0, bh1);
                MMA16816(acc2[j], a2h[s], bl0, bl1);
                MMA16816(acc2[j], a2l[s], bh0, bh1);
            }
        }

        // ---- zb prefetch for this warp's row (L2 hit, hidden by merge) ----
        float2 zbv[8];
        {
            const float2* zp2 = (const float2*)(g_zb + gid * 64);
            #pragma unroll
            for (int nt = 0; nt < 8; nt++) zbv[nt] = zp2[nt * 4 + tg];
        }

        // ---- balanced merge: h0 stores rB-half, h1 stores rA-half ----
        {
            float* dstp = mrg + (h ? 512 : 0);
            int qo = h ? 0 : 2;
            #pragma unroll
            for (int j = 0; j < 8; j++) {
                dstp[(j * 2 + 0) * 32 + lane] = acc2[j][qo + 0];
                dstp[(j * 2 + 1) * 32 + lane] = acc2[j][qo + 1];
            }
        }
        PAIR_BAR(barid);   // barB

        // ---- each warp finalizes its own row ----
        {
            const float* srcp = mrg + (h ? 0 : 512);
            int qo = h ? 2 : 0;
            float o0 = 0.f, o1 = 0.f, o2 = 0.f, o3 = 0.f;
            #pragma unroll
            for (int nt = 0; nt < 8; nt++) {
                float v0 = acc2[nt][qo + 0] + srcp[(nt * 2 + 0) * 32 + lane];
                float v1 = acc2[nt][qo + 1] + srcp[(nt * 2 + 1) * 32 + lane];
                float hv0 = fmaxf(v0 + zbv[nt].x, 0.f);
                float hv1 = fmaxf(v1 + zbv[nt].y, 0.f);
                int c0 = nt * 8 + tg * 2;
                float4 w0 = *(const float4*)&sW3[c0 * 4];
                float4 w1 = *(const float4*)&sW3[(c0 + 1) * 4];
                o0 = fmaf(hv0, w0.x, fmaf(hv1, w1.x, o0));
                o1 = fmaf(hv0, w0.y, fmaf(hv1, w1.y, o1));
                o2 = fmaf(hv0, w0.z, fmaf(hv1, w1.z, o2));
                o3 = fmaf(hv0, w0.w, fmaf(hv1, w1.w, o3));
            }
            #pragma unroll
            for (int d = 1; d <= 2; d <<= 1) {
                o0 += __shfl_xor_sync(0xFFFFFFFF, o0, d);
                o1 += __shfl_xor_sync(0xFFFFFFFF, o1, d);
                o2 += __shfl_xor_sync(0xFFFFFFFF, o2, d);
                o3 += __shfl_xor_sync(0xFFFFFFFF, o3, d);
            }
            if (tg == 0 && grow < N)
                *(float4*)&out_node[(size_t)grow * 4] =
                    make_float4(o0 + b30, o1 + b31, o2 + b32, o3 + b33);
        }

        // ---- write next X hi (sXh dead since barA) ----
        if (nv) {
            #pragma unroll
            for (int it = 0; it < 8; it++) {
                int idx = it * 64 + u;
                int rl  = idx >> 5;
                int q   = idx & 31;
                float4 v = xp[it];
                uint32_t h0v, l0v, h1v, l1v;
                tsplit2(v.x, v.y, h0v, l0v);
                tsplit2(v.z, v.w, h1v, l1v);
                *(uint2*)&sXh[(r0 + rl) * XS + 2 * q] = make_uint2(h0v, h1v);
            }
        }
        PAIR_BAR(barid);   // barC: both warps' merge reads complete

        if (nv) {
            #pragma unroll
            for (int it = 0; it < 8; it++) {
                int idx = it * 64 + u;
                int rl  = idx >> 5;
                int q   = idx & 31;
                float4 v = xp[it];
                uint32_t h0v, l0v, h1v, l1v;
                tsplit2(v.x, v.y, h0v, l0v);
                tsplit2(v.z, v.w, h1v, l1v);
                *(uint2*)&sXl[(r0 + rl) * XS + 2 * q] = make_uint2(l0v, l1v);
            }
        }
        PAIR_BAR(barid);   // barD: staging done before next L1
        unit = nunit;
    }
}

// ---------------------------------------------------------------------------
// Edge table (unchanged)
// ---------------------------------------------------------------------------
__global__ void edge_table_kernel(const float* __restrict__ ed1_b,
                                  const float* __restrict__ ed2_w,
                                  const float* __restrict__ ed2_b)
{
    const int gs = blockIdx.x;
    const int gd = threadIdx.x;
    __shared__ float sAs[64], sb1[64], sw2[64 * 3], sb2[3];
    const int t = threadIdx.x;
    if (t < 64) { sAs[t] = g_As[gs * 64 + t]; sb1[t] = ed1_b[t]; }
    if (t >= 64 && t < 64 + 192) sw2[t - 64] = ed2_w[t - 64];
    if (t < 3) sb2[t] = ed2_b[t];
    __syncthreads();

    float o0 = sb2[0], o1 = sb2[1], o2 = sb2[2];
    const float4* bd4 = (const float4*)(&g_Bd[gd * 64]);
    #pragma unroll
    for (int k4 = 0; k4 < 16; k4++) {
        float4 bv = bd4[k4];
        int k = k4 * 4;
        float h;
        h = fmaxf(sAs[k + 0] + bv.x + sb1[k + 0], 0.f);
        o0 = fmaf(h, sw2[(k + 0) * 3 + 0], o0); o1 = fmaf(h, sw2[(k + 0) * 3 + 1], o1); o2 = fmaf(h, sw2[(k + 0) * 3 + 2], o2);
        h = fmaxf(sAs[k + 1] + bv.y + sb1[k + 1], 0.f);
        o0 = fmaf(h, sw2[(k + 1) * 3 + 0], o0); o1 = fmaf(h, sw2[(k + 1) * 3 + 1], o1); o2 = fmaf(h, sw2[(k + 1) * 3 + 2], o2);
        h = fmaxf(sAs[k + 2] + bv.z + sb1[k + 2], 0.f);
        o0 = fmaf(h, sw2[(k + 2) * 3 + 0], o0); o1 = fmaf(h, sw2[(k + 2) * 3 + 1], o1); o2 = fmaf(h, sw2[(k + 2) * 3 + 2], o2);
        h = fmaxf(sAs[k + 3] + bv.w + sb1[k + 3], 0.f);
        o0 = fmaf(h, sw2[(k + 3) * 3 + 0], o0); o1 = fmaf(h, sw2[(k + 3) * 3 + 1], o1); o2 = fmaf(h, sw2[(k + 3) * 3 + 2], o2);
    }
    g_table[gs * MAXB + gd] = make_float4(o0, o1, o2, 0.f);
}

// ---------------------------------------------------------------------------
// Edge gather: 4 edges/thread, uint8 gid (L1-resident after warmup)
// ---------------------------------------------------------------------------
__global__ void edge_gather_kernel(const int* __restrict__ src, const int* __restrict__ dst,
                                   float* __restrict__ out_edge, int E)
{
    int e = (blockIdx.x * blockDim.x + threadIdx.x) * 4;
    if (e >= E) return;
    if (e + 4 <= E) {
        int4 s = *(const int4*)(src + e);
        int4 d = *(const int4*)(dst + e);
        int gs0 = g_gid8[s.x], gs1 = g_gid8[s.y], gs2 = g_gid8[s.z], gs3 = g_gid8[s.w];
        int gd0 = g_gid8[d.x], gd1 = g_gid8[d.y], gd2 = g_gid8[d.z], gd3 = g_gid8[d.w];
        float4 t0 = g_table[gs0 * MAXB + gd0];
        float4 t1 = g_table[gs1 * MAXB + gd1];
        float4 t2 = g_table[gs2 * MAXB + gd2];
        float4 t3 = g_table[gs3 * MAXB + gd3];
        float* o = out_edge + (size_t)e * 3;
        ((float4*)o)[0] = make_float4(t0.x, t0.y, t0.z, t1.x);
        ((float4*)o)[1] = make_float4(t1.y, t1.z, t2.x, t2.y);
        ((float4*)o)[2] = make_float4(t2.z, t3.x, t3.y, t3.z);
    } else {
        for (int q = e; q < E; q++) {
            float4 t = g_table[g_gid8[src[q]] * MAXB + g_gid8[dst[q]]];
            out_edge[(size_t)q * 3 + 0] = t.x;
            out_edge[(size_t)q * 3 + 1] = t.y;
            out_edge[(size_t)q * 3 + 2] = t.z;
        }
    }
}

// ---------------------------------------------------------------------------
extern "C" void kernel_launch(void* const* d_in, const int* in_sizes, int n_in,
                              void* d_out, int out_size)
{
    const float* z        = (const float*)d_in[0];
    const float* node_emb = (const float*)d_in[1];
    const int*   graph_id = (const int*)  d_in[2];
    const int*   src      = (const int*)  d_in[3];
    const int*   dst      = (const int*)  d_in[4];
    const float* lp_w  = (const float*)d_in[5];
    const float* lp_b  = (const float*)d_in[6];
    const float* nep_w = (const float*)d_in[7];
    const float* nep_b = (const float*)d_in[8];
    const float* nd1_w = (const float*)d_in[9];
    const float* nd1_b = (const float*)d_in[10];
    const float* nd2_w = (const float*)d_in[11];
    const float* nd2_b = (const float*)d_in[12];
    const float* ed1_w = (const float*)d_in[13];
    const float* ed1_b = (const float*)d_in[14];
    const float* ed2_w = (const float*)d_in[15];
    const float* ed2_b = (const float*)d_in[16];
    const float* en1_w = (const float*)d_in[17];
    const float* en1_b = (const float*)d_in[18];
    const float* en2_w = (const float*)d_in[19];
    const float* en2_b = (const float*)d_in[20];
    const float* st1_w = (const float*)d_in[21];
    const float* st1_b = (const float*)d_in[22];
    const float* st2_w = (const float*)d_in[23];
    const float* st2_b = (const float*)d_in[24];

    const int B = in_sizes[0] / 32;
    const int N = in_sizes[1] / 128;
    const int E = in_sizes[3];

    float* out        = (float*)d_out;
    float* out_node   = out;
    float* out_edge   = out + (size_t)N * 4;
    float* out_energy = out + (size_t)N * 4 + (size_t)E * 3;
    float* out_stress = out_energy + (size_t)B * 2;

    cudaFuncSetAttribute(node_mma_kernel, cudaFuncAttributeMaxDynamicSharedMemorySize,
                         NODE_SMEM_BYTES);

    prep_wconv_kernel<<<B + 48, 128>>>(z, lp_w, lp_b, nd1_w, nd1_b, ed1_w,
                                       en1_w, en1_b, en2_w, en2_b,
                                       st1_w, st1_b, st2_w, st2_b,
                                       nep_w, graph_id, N,
                                       out_energy, out_stress, B);

    edge_table_kernel<<<B, 256>>>(ed1_b, ed2_w, ed2_b);

    const int U = (N + 15) / 16;
    node_mma_kernel<<<NODE_GRID, 512, NODE_SMEM_BYTES>>>(node_emb, graph_id,
                                                         nep_b, nd2_w, nd2_b,
                                                         out_node, N, U);

    const int eth = (E + 3) / 4;
    edge_gather_kernel<<<(eth + 255) / 256, 256>>>(src, dst, out_edge, E);
}